// round 1
// baseline (speedup 1.0000x reference)
#include <cuda_runtime.h>
#include <cstdint>

// Problem: ScaledDotProductAttention  B=4 H=16 S=2048 D=64
// outputs: output [B,H,S,D] then attn [B,H,S,S], both f32, concatenated in d_out.

#define NEG_INF -1000000000.0f

static constexpr int Bv = 4, Hv = 16, Sv = 2048, Dv = 64;
static constexpr int BM = 128;     // q rows per CTA
static constexpr int BN = 64;      // kv cols per tile
static constexpr int LDSK = 68;    // padded smem row stride (floats) for 64-wide tiles
static constexpr int THREADS = 256;

__device__ __forceinline__ uint32_t f2tf(float f) {
    uint32_t u;
    asm("cvt.rna.tf32.f32 %0, %1;" : "=r"(u) : "f"(f));
    return u;
}

__device__ __forceinline__ void mma8(float c[4], const uint32_t a[4], uint32_t b0, uint32_t b1) {
    asm volatile(
        "mma.sync.aligned.m16n8k8.row.col.f32.tf32.tf32.f32 "
        "{%0,%1,%2,%3}, {%4,%5,%6,%7}, {%8,%9}, {%0,%1,%2,%3};"
        : "+f"(c[0]), "+f"(c[1]), "+f"(c[2]), "+f"(c[3])
        : "r"(a[0]), "r"(a[1]), "r"(a[2]), "r"(a[3]), "r"(b0), "r"(b1));
}

__global__ __launch_bounds__(THREADS, 2)
void ScaledDotProductAttention_30253749633177_kernel(
    const float* __restrict__ q, const float* __restrict__ k,
    const float* __restrict__ v, const int* __restrict__ mask,
    const float* __restrict__ bias, float* __restrict__ out)
{
    extern __shared__ uint32_t smem[];
    uint32_t* sQ = smem;                 // BM x LDSK (tf32 bits)
    uint32_t* sK = sQ + BM * LDSK;       // BN x LDSK
    uint32_t* sV = sK + BN * LDSK;       // BN x LDSK
    uint32_t* sP = sV + BN * LDSK;       // BM x LDSK (tf32 probs)

    const int b  = blockIdx.x;
    const int qt = blockIdx.y;
    const int h  = blockIdx.z;
    const int tid = threadIdx.x;
    const int wid = tid >> 5;
    const int lane = tid & 31;
    const int g  = lane >> 2;   // groupID (row within 8)
    const int t4 = lane & 3;    // thread-in-group (col quad)
    const int qbase = qt * BM;

    const size_t bh = (size_t)(b * Hv + h);
    const float* qp    = q    + bh * Sv * Dv;
    const float* kp    = k    + bh * Sv * Dv;
    const float* vp    = v    + bh * Sv * Dv;
    const float* biasp = bias + (size_t)h * Sv * Sv;
    const int*   maskp = mask + (size_t)b * Sv * Sv;
    float* op = out + bh * Sv * Dv;
    float* ap = out + (size_t)Bv * Hv * Sv * Dv + bh * (size_t)Sv * Sv;

    // ---- load Q tile once (tf32 converted) ----
    for (int i = tid; i < BM * Dv / 4; i += THREADS) {
        int r = i >> 4;
        int c = (i & 15) * 4;
        float4 f = *reinterpret_cast<const float4*>(qp + (size_t)(qbase + r) * Dv + c);
        uint32_t* d = sQ + r * LDSK + c;
        d[0] = f2tf(f.x); d[1] = f2tf(f.y); d[2] = f2tf(f.z); d[3] = f2tf(f.w);
    }

    const int rowA = qbase + wid * 16 + g;
    const int rowB = rowA + 8;
    const uint32_t* sQa = sQ + (wid * 16 + g) * LDSK + t4;

    float l0 = 0.f, l1 = 0.f;

    // ================= PHASE 1: row sums of exp(score) =================
    for (int kt = 0; kt < Sv / BN; kt++) {
        __syncthreads();
        for (int i = tid; i < BN * Dv / 4; i += THREADS) {
            int r = i >> 4;
            int c = (i & 15) * 4;
            float4 f = *reinterpret_cast<const float4*>(kp + (size_t)(kt * BN + r) * Dv + c);
            uint32_t* d = sK + r * LDSK + c;
            d[0] = f2tf(f.x); d[1] = f2tf(f.y); d[2] = f2tf(f.z); d[3] = f2tf(f.w);
        }
        __syncthreads();

        float acc[8][4];
        #pragma unroll
        for (int nt = 0; nt < 8; nt++) { acc[nt][0] = acc[nt][1] = acc[nt][2] = acc[nt][3] = 0.f; }

        #pragma unroll
        for (int kk = 0; kk < 8; kk++) {
            uint32_t a[4];
            a[0] = sQa[kk * 8];
            a[1] = sQa[kk * 8 + 8 * LDSK];
            a[2] = sQa[kk * 8 + 4];
            a[3] = sQa[kk * 8 + 8 * LDSK + 4];
            #pragma unroll
            for (int nt = 0; nt < 8; nt++) {
                const uint32_t* kb = sK + (nt * 8 + g) * LDSK + kk * 8 + t4;
                mma8(acc[nt], a, kb[0], kb[4]);
            }
        }

        #pragma unroll
        for (int nt = 0; nt < 8; nt++) {
            int col = kt * BN + nt * 8 + 2 * t4;
            float2 bA = *reinterpret_cast<const float2*>(biasp + (size_t)rowA * Sv + col);
            float2 bB = *reinterpret_cast<const float2*>(biasp + (size_t)rowB * Sv + col);
            int2 mA = *reinterpret_cast<const int2*>(maskp + (size_t)rowA * Sv + col);
            int2 mB = *reinterpret_cast<const int2*>(maskp + (size_t)rowB * Sv + col);
            float s0 = (mA.x ? acc[nt][0] * 0.125f : NEG_INF) + bA.x;
            float s1 = (mA.y ? acc[nt][1] * 0.125f : NEG_INF) + bA.y;
            float s2 = (mB.x ? acc[nt][2] * 0.125f : NEG_INF) + bB.x;
            float s3 = (mB.y ? acc[nt][3] * 0.125f : NEG_INF) + bB.y;
            l0 += __expf(fminf(s0, 60.f)) + __expf(fminf(s1, 60.f));
            l1 += __expf(fminf(s2, 60.f)) + __expf(fminf(s3, 60.f));
        }
    }
    l0 += __shfl_xor_sync(0xffffffffu, l0, 1);
    l0 += __shfl_xor_sync(0xffffffffu, l0, 2);
    l1 += __shfl_xor_sync(0xffffffffu, l1, 1);
    l1 += __shfl_xor_sync(0xffffffffu, l1, 2);
    const float il0 = 1.f / l0;
    const float il1 = 1.f / l1;

    // ================= PHASE 2: write attn + O = P @ V =================
    float o[8][4];
    #pragma unroll
    for (int dt = 0; dt < 8; dt++) { o[dt][0] = o[dt][1] = o[dt][2] = o[dt][3] = 0.f; }

    const uint32_t* sPa = sP + (wid * 16 + g) * LDSK + t4;

    for (int kt = 0; kt < Sv / BN; kt++) {
        __syncthreads();
        for (int i = tid; i < BN * Dv / 4; i += THREADS) {
            int r = i >> 4;
            int c = (i & 15) * 4;
            float4 fk = *reinterpret_cast<const float4*>(kp + (size_t)(kt * BN + r) * Dv + c);
            uint32_t* dk = sK + r * LDSK + c;
            dk[0] = f2tf(fk.x); dk[1] = f2tf(fk.y); dk[2] = f2tf(fk.z); dk[3] = f2tf(fk.w);
            float4 fv = *reinterpret_cast<const float4*>(vp + (size_t)(kt * BN + r) * Dv + c);
            uint32_t* dv = sV + r * LDSK + c;
            dv[0] = f2tf(fv.x); dv[1] = f2tf(fv.y); dv[2] = f2tf(fv.z); dv[3] = f2tf(fv.w);
        }
        __syncthreads();

        float acc[8][4];
        #pragma unroll
        for (int nt = 0; nt < 8; nt++) { acc[nt][0] = acc[nt][1] = acc[nt][2] = acc[nt][3] = 0.f; }

        #pragma unroll
        for (int kk = 0; kk < 8; kk++) {
            uint32_t a[4];
            a[0] = sQa[kk * 8];
            a[1] = sQa[kk * 8 + 8 * LDSK];
            a[2] = sQa[kk * 8 + 4];
            a[3] = sQa[kk * 8 + 8 * LDSK + 4];
            #pragma unroll
            for (int nt = 0; nt < 8; nt++) {
                const uint32_t* kb = sK + (nt * 8 + g) * LDSK + kk * 8 + t4;
                mma8(acc[nt], a, kb[0], kb[4]);
            }
        }

        #pragma unroll
        for (int nt = 0; nt < 8; nt++) {
            int col = kt * BN + nt * 8 + 2 * t4;
            float2 bA = *reinterpret_cast<const float2*>(biasp + (size_t)rowA * Sv + col);
            float2 bB = *reinterpret_cast<const float2*>(biasp + (size_t)rowB * Sv + col);
            int2 mA = *reinterpret_cast<const int2*>(maskp + (size_t)rowA * Sv + col);
            int2 mB = *reinterpret_cast<const int2*>(maskp + (size_t)rowB * Sv + col);
            float s0 = (mA.x ? acc[nt][0] * 0.125f : NEG_INF) + bA.x;
            float s1 = (mA.y ? acc[nt][1] * 0.125f : NEG_INF) + bA.y;
            float s2 = (mB.x ? acc[nt][2] * 0.125f : NEG_INF) + bB.x;
            float s3 = (mB.y ? acc[nt][3] * 0.125f : NEG_INF) + bB.y;
            float p0 = __expf(fminf(s0, 60.f)) * il0;
            float p1 = __expf(fminf(s1, 60.f)) * il0;
            float p2 = __expf(fminf(s2, 60.f)) * il1;
            float p3 = __expf(fminf(s3, 60.f)) * il1;

            *reinterpret_cast<float2*>(ap + (size_t)rowA * Sv + col) = make_float2(p0, p1);
            *reinterpret_cast<float2*>(ap + (size_t)rowB * Sv + col) = make_float2(p2, p3);

            uint32_t* pdA = sP + (wid * 16 + g) * LDSK + nt * 8 + 2 * t4;
            uint32_t* pdB = pdA + 8 * LDSK;
            pdA[0] = f2tf(p0); pdA[1] = f2tf(p1);
            pdB[0] = f2tf(p2); pdB[1] = f2tf(p3);
        }
        __syncwarp();

        // O += P(16x64) @ V(64x64); each warp reads only its own sP rows.
        #pragma unroll
        for (int kk = 0; kk < 8; kk++) {
            uint32_t a[4];
            a[0] = sPa[kk * 8];
            a[1] = sPa[kk * 8 + 8 * LDSK];
            a[2] = sPa[kk * 8 + 4];
            a[3] = sPa[kk * 8 + 8 * LDSK + 4];
            #pragma unroll
            for (int dt = 0; dt < 8; dt++) {
                const uint32_t* vb = sV + (kk * 8 + t4) * LDSK + dt * 8 + g;
                mma8(o[dt], a, vb[0], vb[4 * LDSK]);
            }
        }
        // loop-top __syncthreads covers sP/sV hazards for the next tile
    }

    // ---- write O ----
    #pragma unroll
    for (int dt = 0; dt < 8; dt++) {
        int col = dt * 8 + 2 * t4;
        *reinterpret_cast<float2*>(op + (size_t)rowA * Dv + col) = make_float2(o[dt][0], o[dt][1]);
        *reinterpret_cast<float2*>(op + (size_t)rowB * Dv + col) = make_float2(o[dt][2], o[dt][3]);
    }
}

extern "C" void kernel_launch(void* const* d_in, const int* in_sizes, int n_in,
                              void* d_out, int out_size)
{
    const float* q    = (const float*)d_in[0];
    const float* k    = (const float*)d_in[1];
    const float* v    = (const float*)d_in[2];
    const int*   mask = (const int*)d_in[3];
    const float* bias = (const float*)d_in[4];
    float* out = (float*)d_out;

    const int smem_bytes = (BM + BN + BN + BM) * LDSK * 4;  // 104448
    cudaFuncSetAttribute(ScaledDotProductAttention_30253749633177_kernel,
                         cudaFuncAttributeMaxDynamicSharedMemorySize, smem_bytes);

    dim3 grid(Bv, Sv / BM, Hv);  // b fastest (bias reuse), then q-tile (K/V reuse), h outer
    ScaledDotProductAttention_30253749633177_kernel<<<grid, THREADS, smem_bytes>>>(
        q, k, v, mask, bias, out);
}

// round 3
// speedup vs baseline: 1.2342x; 1.2342x over previous
#include <cuda_runtime.h>
#include <cstdint>

// ScaledDotProductAttention  B=4 H=16 S=2048 D=64
// out = [output (B,H,S,D) | attn (B,H,S,S)] f32 concatenated.
// mma.sync tf32, m32n64 warp tiles (4 warps), two-phase (row-sum, then write).

#define NEG_INF -1000000000.0f

static constexpr int Bv = 4, Hv = 16, Sv = 2048, Dv = 64;
static constexpr int BM = 128;     // q rows per CTA
static constexpr int BN = 64;      // kv cols per tile
static constexpr int LDSK = 68;    // padded smem row stride (floats)
static constexpr int THREADS = 128;
static constexpr int NKT = Sv / BN;

__device__ __forceinline__ uint32_t f2tf(float f) {
    uint32_t u;
    asm("cvt.rna.tf32.f32 %0, %1;" : "=r"(u) : "f"(f));
    return u;
}

__device__ __forceinline__ void mma8(float c[4], const uint32_t a[4], uint32_t b0, uint32_t b1) {
    asm volatile(
        "mma.sync.aligned.m16n8k8.row.col.f32.tf32.tf32.f32 "
        "{%0,%1,%2,%3}, {%4,%5,%6,%7}, {%8,%9}, {%0,%1,%2,%3};"
        : "+f"(c[0]), "+f"(c[1]), "+f"(c[2]), "+f"(c[3])
        : "r"(a[0]), "r"(a[1]), "r"(a[2]), "r"(a[3]), "r"(b0), "r"(b1));
}

__global__ __launch_bounds__(THREADS, 2)
void ScaledDotProductAttention_30253749633177_kernel(
    const float* __restrict__ q, const float* __restrict__ k,
    const float* __restrict__ v, const int* __restrict__ mask,
    const float* __restrict__ bias, float* __restrict__ out)
{
    extern __shared__ uint32_t smem[];
    uint32_t* sQ = smem;                 // BM x LDSK (tf32 bits)
    uint32_t* sK = sQ + BM * LDSK;       // BN x LDSK
    uint32_t* sV = sK + BN * LDSK;       // BN x LDSK (row-major [s][d])
    uint32_t* sP = sV + BN * LDSK;       // BM x LDSK (tf32 probs)

    const int b  = blockIdx.x;
    const int qt = blockIdx.y;
    const int h  = blockIdx.z;
    const int tid = threadIdx.x;
    const int wid = tid >> 5;
    const int lane = tid & 31;
    const int g  = lane >> 2;   // row within 8
    const int t4 = lane & 3;    // col quad
    const int qbase = qt * BM;
    const int wrow = wid * 32;  // warp's 32-row block

    const size_t bh = (size_t)(b * Hv + h);
    const float* qp    = q    + bh * Sv * Dv;
    const float* kp    = k    + bh * Sv * Dv;
    const float* vp    = v    + bh * Sv * Dv;
    const float* biasp = bias + (size_t)h * Sv * Sv;
    const int*   maskp = mask + (size_t)b * Sv * Sv;
    float* op = out + bh * Sv * Dv;
    float* ap = out + (size_t)Bv * Hv * Sv * Dv + bh * (size_t)Sv * Sv;

    // ---- load Q tile once (tf32 converted) ----
    for (int i = tid; i < BM * Dv / 4; i += THREADS) {
        int r = i >> 4;
        int c = (i & 15) * 4;
        float4 f = *reinterpret_cast<const float4*>(qp + (size_t)(qbase + r) * Dv + c);
        uint32_t* d = sQ + r * LDSK + c;
        d[0] = f2tf(f.x); d[1] = f2tf(f.y); d[2] = f2tf(f.z); d[3] = f2tf(f.w);
    }

    // per-warp A-row bases (2 m16 blocks)
    const uint32_t* sQa0 = sQ + (wrow + g) * LDSK + t4;
    const uint32_t* sQa1 = sQ + (wrow + 16 + g) * LDSK + t4;

    // global rows this thread owns in epilogues
    const int rA0 = qbase + wrow + g;        // mb=0 rows g, g+8
    const int rA1 = qbase + wrow + 16 + g;   // mb=1 rows g+16, g+24

    float ls[2][2] = {{0.f, 0.f}, {0.f, 0.f}};

    // ================= PHASE 1: row sums of exp(score) =================
    for (int kt = 0; kt < NKT; kt++) {
        __syncthreads();
        for (int i = tid; i < BN * Dv / 4; i += THREADS) {
            int r = i >> 4;
            int c = (i & 15) * 4;
            float4 f = *reinterpret_cast<const float4*>(kp + (size_t)(kt * BN + r) * Dv + c);
            uint32_t* d = sK + r * LDSK + c;
            d[0] = f2tf(f.x); d[1] = f2tf(f.y); d[2] = f2tf(f.z); d[3] = f2tf(f.w);
        }
        __syncthreads();

        float acc[2][8][4];
        #pragma unroll
        for (int mb = 0; mb < 2; mb++)
            #pragma unroll
            for (int nt = 0; nt < 8; nt++)
                acc[mb][nt][0] = acc[mb][nt][1] = acc[mb][nt][2] = acc[mb][nt][3] = 0.f;

        #pragma unroll
        for (int kk = 0; kk < 8; kk++) {
            uint32_t a0[4], a1[4];
            a0[0] = sQa0[kk * 8];               a1[0] = sQa1[kk * 8];
            a0[1] = sQa0[kk * 8 + 8 * LDSK];    a1[1] = sQa1[kk * 8 + 8 * LDSK];
            a0[2] = sQa0[kk * 8 + 4];           a1[2] = sQa1[kk * 8 + 4];
            a0[3] = sQa0[kk * 8 + 8 * LDSK + 4];a1[3] = sQa1[kk * 8 + 8 * LDSK + 4];
            #pragma unroll
            for (int nt = 0; nt < 8; nt++) {
                const uint32_t* kb = sK + (nt * 8 + g) * LDSK + kk * 8 + t4;
                uint32_t b0 = kb[0], b1 = kb[4];
                mma8(acc[0][nt], a0, b0, b1);
                mma8(acc[1][nt], a1, b0, b1);
            }
        }

        #pragma unroll
        for (int mb = 0; mb < 2; mb++) {
            const int rowA = (mb ? rA1 : rA0);
            const int rowB = rowA + 8;
            #pragma unroll
            for (int nt = 0; nt < 8; nt++) {
                int col = kt * BN + nt * 8 + 2 * t4;
                float2 bA = *reinterpret_cast<const float2*>(biasp + (size_t)rowA * Sv + col);
                float2 bB = *reinterpret_cast<const float2*>(biasp + (size_t)rowB * Sv + col);
                int2 mA = *reinterpret_cast<const int2*>(maskp + (size_t)rowA * Sv + col);
                int2 mB = *reinterpret_cast<const int2*>(maskp + (size_t)rowB * Sv + col);
                float s0 = (mA.x ? acc[mb][nt][0] * 0.125f : NEG_INF) + bA.x;
                float s1 = (mA.y ? acc[mb][nt][1] * 0.125f : NEG_INF) + bA.y;
                float s2 = (mB.x ? acc[mb][nt][2] * 0.125f : NEG_INF) + bB.x;
                float s3 = (mB.y ? acc[mb][nt][3] * 0.125f : NEG_INF) + bB.y;
                ls[mb][0] += __expf(fminf(s0, 60.f)) + __expf(fminf(s1, 60.f));
                ls[mb][1] += __expf(fminf(s2, 60.f)) + __expf(fminf(s3, 60.f));
            }
        }
    }
    // reduce across the t4 quad (warp spans full 64-col width)
    #pragma unroll
    for (int mb = 0; mb < 2; mb++) {
        ls[mb][0] += __shfl_xor_sync(0xffffffffu, ls[mb][0], 1);
        ls[mb][0] += __shfl_xor_sync(0xffffffffu, ls[mb][0], 2);
        ls[mb][1] += __shfl_xor_sync(0xffffffffu, ls[mb][1], 1);
        ls[mb][1] += __shfl_xor_sync(0xffffffffu, ls[mb][1], 2);
    }
    const float il[2][2] = {{1.f / ls[0][0], 1.f / ls[0][1]},
                            {1.f / ls[1][0], 1.f / ls[1][1]}};

    // ================= PHASE 2: attn write + O = P @ V =================
    float o[2][8][4];
    #pragma unroll
    for (int mb = 0; mb < 2; mb++)
        #pragma unroll
        for (int dt = 0; dt < 8; dt++)
            o[mb][dt][0] = o[mb][dt][1] = o[mb][dt][2] = o[mb][dt][3] = 0.f;

    const uint32_t* sPa0 = sP + (wrow + g) * LDSK + t4;
    const uint32_t* sPa1 = sP + (wrow + 16 + g) * LDSK + t4;

    for (int kt = 0; kt < NKT; kt++) {
        __syncthreads();
        for (int i = tid; i < BN * Dv / 4; i += THREADS) {
            int r = i >> 4;
            int c = (i & 15) * 4;
            float4 fk = *reinterpret_cast<const float4*>(kp + (size_t)(kt * BN + r) * Dv + c);
            uint32_t* dk = sK + r * LDSK + c;
            dk[0] = f2tf(fk.x); dk[1] = f2tf(fk.y); dk[2] = f2tf(fk.z); dk[3] = f2tf(fk.w);
            float4 fv = *reinterpret_cast<const float4*>(vp + (size_t)(kt * BN + r) * Dv + c);
            uint32_t* dv = sV + r * LDSK + c;
            dv[0] = f2tf(fv.x); dv[1] = f2tf(fv.y); dv[2] = f2tf(fv.z); dv[3] = f2tf(fv.w);
        }
        __syncthreads();

        float acc[2][8][4];
        #pragma unroll
        for (int mb = 0; mb < 2; mb++)
            #pragma unroll
            for (int nt = 0; nt < 8; nt++)
                acc[mb][nt][0] = acc[mb][nt][1] = acc[mb][nt][2] = acc[mb][nt][3] = 0.f;

        #pragma unroll
        for (int kk = 0; kk < 8; kk++) {
            uint32_t a0[4], a1[4];
            a0[0] = sQa0[kk * 8];               a1[0] = sQa1[kk * 8];
            a0[1] = sQa0[kk * 8 + 8 * LDSK];    a1[1] = sQa1[kk * 8 + 8 * LDSK];
            a0[2] = sQa0[kk * 8 + 4];           a1[2] = sQa1[kk * 8 + 4];
            a0[3] = sQa0[kk * 8 + 8 * LDSK + 4];a1[3] = sQa1[kk * 8 + 8 * LDSK + 4];
            #pragma unroll
            for (int nt = 0; nt < 8; nt++) {
                const uint32_t* kb = sK + (nt * 8 + g) * LDSK + kk * 8 + t4;
                uint32_t b0 = kb[0], b1 = kb[4];
                mma8(acc[0][nt], a0, b0, b1);
                mma8(acc[1][nt], a1, b0, b1);
            }
        }

        #pragma unroll
        for (int mb = 0; mb < 2; mb++) {
            const int rowA = (mb ? rA1 : rA0);
            const int rowB = rowA + 8;
            const int lr = wrow + mb * 16 + g;   // local row in sP
            #pragma unroll
            for (int nt = 0; nt < 8; nt++) {
                int col = kt * BN + nt * 8 + 2 * t4;
                float2 bA = *reinterpret_cast<const float2*>(biasp + (size_t)rowA * Sv + col);
                float2 bB = *reinterpret_cast<const float2*>(biasp + (size_t)rowB * Sv + col);
                int2 mA = *reinterpret_cast<const int2*>(maskp + (size_t)rowA * Sv + col);
                int2 mB = *reinterpret_cast<const int2*>(maskp + (size_t)rowB * Sv + col);
                float s0 = (mA.x ? acc[mb][nt][0] * 0.125f : NEG_INF) + bA.x;
                float s1 = (mA.y ? acc[mb][nt][1] * 0.125f : NEG_INF) + bA.y;
                float s2 = (mB.x ? acc[mb][nt][2] * 0.125f : NEG_INF) + bB.x;
                float s3 = (mB.y ? acc[mb][nt][3] * 0.125f : NEG_INF) + bB.y;
                float p0 = __expf(fminf(s0, 60.f)) * il[mb][0];
                float p1 = __expf(fminf(s1, 60.f)) * il[mb][0];
                float p2 = __expf(fminf(s2, 60.f)) * il[mb][1];
                float p3 = __expf(fminf(s3, 60.f)) * il[mb][1];

                *reinterpret_cast<float2*>(ap + (size_t)rowA * Sv + col) = make_float2(p0, p1);
                *reinterpret_cast<float2*>(ap + (size_t)rowB * Sv + col) = make_float2(p2, p3);

                uint32_t* pdA = sP + lr * LDSK + nt * 8 + 2 * t4;
                uint32_t* pdB = pdA + 8 * LDSK;
                pdA[0] = f2tf(p0); pdA[1] = f2tf(p1);
                pdB[0] = f2tf(p2); pdB[1] = f2tf(p3);
            }
        }
        __syncwarp();   // each warp reads only its own sP rows

        #pragma unroll
        for (int kk = 0; kk < 8; kk++) {
            uint32_t a0[4], a1[4];
            a0[0] = sPa0[kk * 8];               a1[0] = sPa1[kk * 8];
            a0[1] = sPa0[kk * 8 + 8 * LDSK];    a1[1] = sPa1[kk * 8 + 8 * LDSK];
            a0[2] = sPa0[kk * 8 + 4];           a1[2] = sPa1[kk * 8 + 4];
            a0[3] = sPa0[kk * 8 + 8 * LDSK + 4];a1[3] = sPa1[kk * 8 + 8 * LDSK + 4];
            #pragma unroll
            for (int dt = 0; dt < 8; dt++) {
                const uint32_t* vb = sV + (kk * 8 + t4) * LDSK + dt * 8 + g;
                uint32_t b0 = vb[0], b1 = vb[4 * LDSK];
                mma8(o[0][dt], a0, b0, b1);
                mma8(o[1][dt], a1, b0, b1);
            }
        }
        // loop-top __syncthreads covers sK/sV hazards for next tile
    }

    // ---- write O ----
    #pragma unroll
    for (int mb = 0; mb < 2; mb++) {
        const int rowA = (mb ? rA1 : rA0);
        const int rowB = rowA + 8;
        #pragma unroll
        for (int dt = 0; dt < 8; dt++) {
            int col = dt * 8 + 2 * t4;
            *reinterpret_cast<float2*>(op + (size_t)rowA * Dv + col) =
                make_float2(o[mb][dt][0], o[mb][dt][1]);
            *reinterpret_cast<float2*>(op + (size_t)rowB * Dv + col) =
                make_float2(o[mb][dt][2], o[mb][dt][3]);
        }
    }
}

extern "C" void kernel_launch(void* const* d_in, const int* in_sizes, int n_in,
                              void* d_out, int out_size)
{
    const float* q    = (const float*)d_in[0];
    const float* k    = (const float*)d_in[1];
    const float* v    = (const float*)d_in[2];
    const int*   mask = (const int*)d_in[3];
    const float* bias = (const float*)d_in[4];
    float* out = (float*)d_out;

    const int smem_bytes = (BM + BN + BN + BM) * LDSK * 4;  // 104448
    cudaFuncSetAttribute(ScaledDotProductAttention_30253749633177_kernel,
                         cudaFuncAttributeMaxDynamicSharedMemorySize, smem_bytes);

    dim3 grid(Bv, Sv / BM, Hv);  // b fastest (bias reuse), then q-tile (K/V reuse), h outer
    ScaledDotProductAttention_30253749633177_kernel<<<grid, THREADS, smem_bytes>>>(
        q, k, v, mask, bias, out);
}

// round 5
// speedup vs baseline: 1.4260x; 1.1553x over previous
#include <cuda_runtime.h>
#include <cstdint>

// ScaledDotProductAttention  B=4 H=16 S=2048 D=64
// out = [output (B,H,S,D) | attn (B,H,S,S)] f32.
// Single-pass mma.sync tf32 (m32n64 warp tiles), cp.async double-buffered K/V,
// shfl P remap (no sP smem), rna tf32 rounding, unnormalized attn + normalize pass.

#define NEG_INF -1000000000.0f

static constexpr int Bv = 4, Hv = 16, Sv = 2048, Dv = 64;
static constexpr int BM = 128, BN = 64, THREADS = 128, NKT = Sv / BN;
static constexpr int LDSK = 68;  // padded row stride (floats)

// smem byte offsets: Q | K0 | K1 | V0 | V1
static constexpr int SQ  = 0;
static constexpr int TILE_B = BN * LDSK * 4;          // 17408
static constexpr int SK0 = BM * LDSK * 4;             // 34816
static constexpr int SK1 = SK0 + TILE_B;
static constexpr int SV0 = SK1 + TILE_B;
static constexpr int SV1 = SV0 + TILE_B;
static constexpr int SMEM_TOTAL = SV1 + TILE_B;       // 104448

__device__ float g_inv[Bv * Hv * Sv];   // per-row 1/lsum scratch

__device__ __forceinline__ uint32_t s2u(const void* p) {
    uint32_t a;
    asm("{ .reg .u64 t; cvta.to.shared.u64 t, %1; cvt.u32.u64 %0, t; }" : "=r"(a) : "l"(p));
    return a;
}
__device__ __forceinline__ void cpa16(uint32_t dst, const void* src) {
    asm volatile("cp.async.cg.shared.global [%0], [%1], 16;" :: "r"(dst), "l"(src));
}
__device__ __forceinline__ uint32_t f2tf(float f) {
    uint32_t u;
    asm("cvt.rna.tf32.f32 %0, %1;" : "=r"(u) : "f"(f));
    return u;
}
__device__ __forceinline__ void mma8(float c[4], const uint32_t a[4], uint32_t b0, uint32_t b1) {
    asm volatile(
        "mma.sync.aligned.m16n8k8.row.col.f32.tf32.tf32.f32 "
        "{%0,%1,%2,%3}, {%4,%5,%6,%7}, {%8,%9}, {%0,%1,%2,%3};"
        : "+f"(c[0]), "+f"(c[1]), "+f"(c[2]), "+f"(c[3])
        : "r"(a[0]), "r"(a[1]), "r"(a[2]), "r"(a[3]), "r"(b0), "r"(b1));
}

__global__ __launch_bounds__(THREADS, 2)
void ScaledDotProductAttention_30253749633177_kernel(
    const float* __restrict__ q, const float* __restrict__ k,
    const float* __restrict__ v, const int* __restrict__ mask,
    const float* __restrict__ bias, float* __restrict__ out)
{
    extern __shared__ char smem[];
    const uint32_t sb = s2u(smem);
    uint32_t* sQ = (uint32_t*)(smem + SQ);

    const int b  = blockIdx.x, qt = blockIdx.y, h = blockIdx.z;
    const int tid = threadIdx.x;
    const int wid = tid >> 5, lane = tid & 31;
    const int g = lane >> 2, t4 = lane & 3;
    const int qbase = qt * BM, wrow = wid * 32;

    const size_t bh = (size_t)(b * Hv + h);
    const float* qp    = q + bh * Sv * Dv;
    const float* kp    = k + bh * Sv * Dv;
    const float* vp    = v + bh * Sv * Dv;
    const float* biasp = bias + (size_t)h * Sv * Sv;
    const int*   maskp = mask + (size_t)b * Sv * Sv;
    float* op = out + bh * Sv * Dv;
    float* ap = out + (size_t)Bv * Hv * Sv * Dv + bh * (size_t)Sv * Sv;

    // ---- group 0: Q + K0 + V0 ----
    for (int i = tid; i < BM * Dv / 4; i += THREADS) {
        int r = i >> 4, c = (i & 15) * 4;
        cpa16(sb + SQ + (r * LDSK + c) * 4, qp + (size_t)(qbase + r) * Dv + c);
    }
    for (int i = tid; i < BN * Dv / 4; i += THREADS) {
        int r = i >> 4, c = (i & 15) * 4;
        cpa16(sb + SK0 + (r * LDSK + c) * 4, kp + (size_t)r * Dv + c);
        cpa16(sb + SV0 + (r * LDSK + c) * 4, vp + (size_t)r * Dv + c);
    }
    asm volatile("cp.async.commit_group;" ::: "memory");

    // wait group 0, then rna-convert Q in place (once)
    asm volatile("cp.async.wait_group 0;" ::: "memory");
    __syncthreads();
    for (int i = tid; i < BM * Dv / 4; i += THREADS) {
        int r = i >> 4, c = (i & 15) * 4;
        uint32_t* p = sQ + r * LDSK + c;
        float4 f = *reinterpret_cast<const float4*>(p);
        p[0] = f2tf(f.x); p[1] = f2tf(f.y); p[2] = f2tf(f.z); p[3] = f2tf(f.w);
    }
    __syncthreads();

    const uint32_t* sQa0 = sQ + (wrow + g) * LDSK + t4;
    const uint32_t* sQa1 = sQ + (wrow + 16 + g) * LDSK + t4;
    const int rA0 = qbase + wrow + g;
    const int rA1 = qbase + wrow + 16 + g;

    const int srcA = (lane & 28) | (t4 >> 1);
    const int srcB = srcA + 2;
    const int sel  = t4 & 1;

    float ls[2][2] = {{0.f, 0.f}, {0.f, 0.f}};
    float o[2][8][4];
    #pragma unroll
    for (int mb = 0; mb < 2; mb++)
        #pragma unroll
        for (int dt = 0; dt < 8; dt++)
            o[mb][dt][0] = o[mb][dt][1] = o[mb][dt][2] = o[mb][dt][3] = 0.f;

    for (int kt = 0; kt < NKT; kt++) {
        const int cur = kt & 1;
        // prefetch next tile into the other buffer
        if (kt + 1 < NKT) {
            const uint32_t dk = sb + (cur ? SK0 : SK1);
            const uint32_t dv = sb + (cur ? SV0 : SV1);
            const float* ks = kp + (size_t)(kt + 1) * BN * Dv;
            const float* vs = vp + (size_t)(kt + 1) * BN * Dv;
            for (int i = tid; i < BN * Dv / 4; i += THREADS) {
                int r = i >> 4, c = (i & 15) * 4;
                cpa16(dk + (r * LDSK + c) * 4, ks + (size_t)r * Dv + c);
                cpa16(dv + (r * LDSK + c) * 4, vs + (size_t)r * Dv + c);
            }
            asm volatile("cp.async.commit_group;" ::: "memory");
            asm volatile("cp.async.wait_group 1;" ::: "memory");
        } else {
            asm volatile("cp.async.wait_group 0;" ::: "memory");
        }
        __syncthreads();

        const float* sK = (float*)(smem + (cur ? SK1 : SK0));
        const float* sV = (float*)(smem + (cur ? SV1 : SV0));

        // ---- QK ----
        float acc[2][8][4];
        #pragma unroll
        for (int mb = 0; mb < 2; mb++)
            #pragma unroll
            for (int nt = 0; nt < 8; nt++)
                acc[mb][nt][0] = acc[mb][nt][1] = acc[mb][nt][2] = acc[mb][nt][3] = 0.f;

        #pragma unroll
        for (int kk = 0; kk < 8; kk++) {
            uint32_t a0[4], a1[4];
            a0[0] = sQa0[kk * 8];                a1[0] = sQa1[kk * 8];
            a0[1] = sQa0[kk * 8 + 8 * LDSK];     a1[1] = sQa1[kk * 8 + 8 * LDSK];
            a0[2] = sQa0[kk * 8 + 4];            a1[2] = sQa1[kk * 8 + 4];
            a0[3] = sQa0[kk * 8 + 8 * LDSK + 4]; a1[3] = sQa1[kk * 8 + 8 * LDSK + 4];
            #pragma unroll
            for (int nt = 0; nt < 8; nt++) {
                const float* kb = sK + (nt * 8 + g) * LDSK + kk * 8 + t4;
                uint32_t b0 = f2tf(kb[0]), b1 = f2tf(kb[4]);
                mma8(acc[0][nt], a0, b0, b1);
                mma8(acc[1][nt], a1, b0, b1);
            }
        }

        // ---- epilogue: e = exp(masked score + bias), unnormalized attn write ----
        #pragma unroll
        for (int mb = 0; mb < 2; mb++) {
            const int rowA = (mb ? rA1 : rA0);
            const int rowB = rowA + 8;
            #pragma unroll
            for (int nt = 0; nt < 8; nt++) {
                int col = kt * BN + nt * 8 + 2 * t4;
                float2 bA = *reinterpret_cast<const float2*>(biasp + (size_t)rowA * Sv + col);
                float2 bB = *reinterpret_cast<const float2*>(biasp + (size_t)rowB * Sv + col);
                int2 mA = *reinterpret_cast<const int2*>(maskp + (size_t)rowA * Sv + col);
                int2 mB = *reinterpret_cast<const int2*>(maskp + (size_t)rowB * Sv + col);
                float s0 = (mA.x ? acc[mb][nt][0] * 0.125f : NEG_INF) + bA.x;
                float s1 = (mA.y ? acc[mb][nt][1] * 0.125f : NEG_INF) + bA.y;
                float s2 = (mB.x ? acc[mb][nt][2] * 0.125f : NEG_INF) + bB.x;
                float s3 = (mB.y ? acc[mb][nt][3] * 0.125f : NEG_INF) + bB.y;
                float e0 = __expf(fminf(s0, 60.f));
                float e1 = __expf(fminf(s1, 60.f));
                float e2 = __expf(fminf(s2, 60.f));
                float e3 = __expf(fminf(s3, 60.f));
                *reinterpret_cast<float2*>(ap + (size_t)rowA * Sv + col) = make_float2(e0, e1);
                *reinterpret_cast<float2*>(ap + (size_t)rowB * Sv + col) = make_float2(e2, e3);
                ls[mb][0] += e0 + e1;
                ls[mb][1] += e2 + e3;
                acc[mb][nt][0] = e0; acc[mb][nt][1] = e1;
                acc[mb][nt][2] = e2; acc[mb][nt][3] = e3;
            }
        }

        // ---- PV: remap acc (C-frag) -> A-frag via shuffles, rna-round, accumulate O ----
        #pragma unroll
        for (int kk = 0; kk < 8; kk++) {
            uint32_t a0[4], a1[4];
            {
                float u0 = __shfl_sync(0xffffffffu, acc[0][kk][0], srcA);
                float u1 = __shfl_sync(0xffffffffu, acc[0][kk][1], srcA);
                float u2 = __shfl_sync(0xffffffffu, acc[0][kk][2], srcA);
                float u3 = __shfl_sync(0xffffffffu, acc[0][kk][3], srcA);
                float w0 = __shfl_sync(0xffffffffu, acc[0][kk][0], srcB);
                float w1 = __shfl_sync(0xffffffffu, acc[0][kk][1], srcB);
                float w2 = __shfl_sync(0xffffffffu, acc[0][kk][2], srcB);
                float w3 = __shfl_sync(0xffffffffu, acc[0][kk][3], srcB);
                a0[0] = f2tf(sel ? u1 : u0);  a0[1] = f2tf(sel ? u3 : u2);
                a0[2] = f2tf(sel ? w1 : w0);  a0[3] = f2tf(sel ? w3 : w2);
            }
            {
                float u0 = __shfl_sync(0xffffffffu, acc[1][kk][0], srcA);
                float u1 = __shfl_sync(0xffffffffu, acc[1][kk][1], srcA);
                float u2 = __shfl_sync(0xffffffffu, acc[1][kk][2], srcA);
                float u3 = __shfl_sync(0xffffffffu, acc[1][kk][3], srcA);
                float w0 = __shfl_sync(0xffffffffu, acc[1][kk][0], srcB);
                float w1 = __shfl_sync(0xffffffffu, acc[1][kk][1], srcB);
                float w2 = __shfl_sync(0xffffffffu, acc[1][kk][2], srcB);
                float w3 = __shfl_sync(0xffffffffu, acc[1][kk][3], srcB);
                a1[0] = f2tf(sel ? u1 : u0);  a1[1] = f2tf(sel ? u3 : u2);
                a1[2] = f2tf(sel ? w1 : w0);  a1[3] = f2tf(sel ? w3 : w2);
            }
            #pragma unroll
            for (int dt = 0; dt < 8; dt++) {
                const float* vb = sV + (kk * 8 + t4) * LDSK + dt * 8 + g;
                uint32_t b0 = f2tf(vb[0]), b1 = f2tf(vb[4 * LDSK]);
                mma8(o[0][dt], a0, b0, b1);
                mma8(o[1][dt], a1, b0, b1);
            }
        }
        __syncthreads();  // done reading bufs before next iter's prefetch overwrites
    }

    // ---- row sums -> inverses (reduce across t4 quad) ----
    #pragma unroll
    for (int mb = 0; mb < 2; mb++) {
        ls[mb][0] += __shfl_xor_sync(0xffffffffu, ls[mb][0], 1);
        ls[mb][0] += __shfl_xor_sync(0xffffffffu, ls[mb][0], 2);
        ls[mb][1] += __shfl_xor_sync(0xffffffffu, ls[mb][1], 1);
        ls[mb][1] += __shfl_xor_sync(0xffffffffu, ls[mb][1], 2);
    }
    const float il[2][2] = {{1.f / ls[0][0], 1.f / ls[0][1]},
                            {1.f / ls[1][0], 1.f / ls[1][1]}};

    // stash inverses for the normalize kernel
    if (t4 == 0) {
        #pragma unroll
        for (int mb = 0; mb < 2; mb++) {
            const int rowA = (mb ? rA1 : rA0);
            g_inv[bh * Sv + rowA]     = il[mb][0];
            g_inv[bh * Sv + rowA + 8] = il[mb][1];
        }
    }

    // ---- write O (normalized) ----
    #pragma unroll
    for (int mb = 0; mb < 2; mb++) {
        const int rowA = (mb ? rA1 : rA0);
        const int rowB = rowA + 8;
        #pragma unroll
        for (int dt = 0; dt < 8; dt++) {
            int col = dt * 8 + 2 * t4;
            *reinterpret_cast<float2*>(op + (size_t)rowA * Dv + col) =
                make_float2(o[mb][dt][0] * il[mb][0], o[mb][dt][1] * il[mb][0]);
            *reinterpret_cast<float2*>(op + (size_t)rowB * Dv + col) =
                make_float2(o[mb][dt][2] * il[mb][1], o[mb][dt][3] * il[mb][1]);
        }
    }
}

// ---- pass 2: attn[row] *= 1/lsum[row] (pure stream) ----
__global__ __launch_bounds__(256)
void sdpa_normalize_kernel(float4* __restrict__ attn, int64_t total4)
{
    int64_t stride = (int64_t)gridDim.x * blockDim.x;
    for (int64_t i = (int64_t)blockIdx.x * blockDim.x + threadIdx.x; i < total4; i += stride) {
        float inv = g_inv[i >> 9];   // 512 float4 per 2048-col row
        float4 vv = attn[i];
        vv.x *= inv; vv.y *= inv; vv.z *= inv; vv.w *= inv;
        attn[i] = vv;
    }
}

extern "C" void kernel_launch(void* const* d_in, const int* in_sizes, int n_in,
                              void* d_out, int out_size)
{
    const float* q    = (const float*)d_in[0];
    const float* k    = (const float*)d_in[1];
    const float* v    = (const float*)d_in[2];
    const int*   mask = (const int*)d_in[3];
    const float* bias = (const float*)d_in[4];
    float* out = (float*)d_out;

    cudaFuncSetAttribute(ScaledDotProductAttention_30253749633177_kernel,
                         cudaFuncAttributeMaxDynamicSharedMemorySize, SMEM_TOTAL);

    dim3 grid(Bv, Sv / BM, Hv);
    ScaledDotProductAttention_30253749633177_kernel<<<grid, THREADS, SMEM_TOTAL>>>(
        q, k, v, mask, bias, out);

    float4* attn = (float4*)(out + (size_t)Bv * Hv * Sv * Dv);
    int64_t total4 = (int64_t)Bv * Hv * Sv * Sv / 4;
    sdpa_normalize_kernel<<<8192, 256>>>(attn, total4);
}

// round 6
// speedup vs baseline: 1.5158x; 1.0630x over previous
#include <cuda_runtime.h>
#include <cstdint>

// ScaledDotProductAttention  B=4 H=16 S=2048 D=64
// out = [output (B,H,S,D) | attn (B,H,S,S)] f32.
// Single-pass mma.sync tf32 (m32n64 warp tiles), cp.async double-buffered K/V,
// shfl P remap, rna tf32 rounding, unnormalized attn + normalize pass.
// R6: grid collapsed to (b*h, qt) for joint mask+bias L2 reuse; streaming attn stores.

#define NEG_INF -1000000000.0f

static constexpr int Bv = 4, Hv = 16, Sv = 2048, Dv = 64;
static constexpr int BM = 128, BN = 64, THREADS = 128, NKT = Sv / BN;
static constexpr int LDSK = 68;  // padded row stride (floats)

// smem byte offsets: Q | K0 | K1 | V0 | V1
static constexpr int SQ  = 0;
static constexpr int TILE_B = BN * LDSK * 4;          // 17408
static constexpr int SK0 = BM * LDSK * 4;             // 34816
static constexpr int SK1 = SK0 + TILE_B;
static constexpr int SV0 = SK1 + TILE_B;
static constexpr int SV1 = SV0 + TILE_B;
static constexpr int SMEM_TOTAL = SV1 + TILE_B;       // 104448

__device__ float g_inv[Bv * Hv * Sv];   // per-row 1/lsum scratch

__device__ __forceinline__ uint32_t s2u(const void* p) {
    uint32_t a;
    asm("{ .reg .u64 t; cvta.to.shared.u64 t, %1; cvt.u32.u64 %0, t; }" : "=r"(a) : "l"(p));
    return a;
}
__device__ __forceinline__ void cpa16(uint32_t dst, const void* src) {
    asm volatile("cp.async.cg.shared.global [%0], [%1], 16;" :: "r"(dst), "l"(src));
}
__device__ __forceinline__ uint32_t f2tf(float f) {
    uint32_t u;
    asm("cvt.rna.tf32.f32 %0, %1;" : "=r"(u) : "f"(f));
    return u;
}
__device__ __forceinline__ void st_cs2(float* p, float x, float y) {
    asm volatile("st.global.cs.v2.f32 [%0], {%1, %2};" :: "l"(p), "f"(x), "f"(y) : "memory");
}
__device__ __forceinline__ void mma8(float c[4], const uint32_t a[4], uint32_t b0, uint32_t b1) {
    asm volatile(
        "mma.sync.aligned.m16n8k8.row.col.f32.tf32.tf32.f32 "
        "{%0,%1,%2,%3}, {%4,%5,%6,%7}, {%8,%9}, {%0,%1,%2,%3};"
        : "+f"(c[0]), "+f"(c[1]), "+f"(c[2]), "+f"(c[3])
        : "r"(a[0]), "r"(a[1]), "r"(a[2]), "r"(a[3]), "r"(b0), "r"(b1));
}

__global__ __launch_bounds__(THREADS, 2)
void ScaledDotProductAttention_30253749633177_kernel(
    const float* __restrict__ q, const float* __restrict__ k,
    const float* __restrict__ v, const int* __restrict__ mask,
    const float* __restrict__ bias, float* __restrict__ out)
{
    extern __shared__ char smem[];
    const uint32_t sb = s2u(smem);
    uint32_t* sQ = (uint32_t*)(smem + SQ);

    const int b  = blockIdx.x & 3;      // (b,h) collapsed: one x-slice = all 64 (b,h)
    const int h  = blockIdx.x >> 2;     // for one qt -> mask+bias co-resident in L2
    const int qt = blockIdx.y;
    const int tid = threadIdx.x;
    const int wid = tid >> 5, lane = tid & 31;
    const int g = lane >> 2, t4 = lane & 3;
    const int qbase = qt * BM, wrow = wid * 32;

    const size_t bh = (size_t)(b * Hv + h);
    const float* qp    = q + bh * Sv * Dv;
    const float* kp    = k + bh * Sv * Dv;
    const float* vp    = v + bh * Sv * Dv;
    const float* biasp = bias + (size_t)h * Sv * Sv;
    const int*   maskp = mask + (size_t)b * Sv * Sv;
    float* op = out + bh * Sv * Dv;
    float* ap = out + (size_t)Bv * Hv * Sv * Dv + bh * (size_t)Sv * Sv;

    // ---- group 0: Q + K0 + V0 ----
    for (int i = tid; i < BM * Dv / 4; i += THREADS) {
        int r = i >> 4, c = (i & 15) * 4;
        cpa16(sb + SQ + (r * LDSK + c) * 4, qp + (size_t)(qbase + r) * Dv + c);
    }
    for (int i = tid; i < BN * Dv / 4; i += THREADS) {
        int r = i >> 4, c = (i & 15) * 4;
        cpa16(sb + SK0 + (r * LDSK + c) * 4, kp + (size_t)r * Dv + c);
        cpa16(sb + SV0 + (r * LDSK + c) * 4, vp + (size_t)r * Dv + c);
    }
    asm volatile("cp.async.commit_group;" ::: "memory");

    // wait group 0, then rna-convert Q in place (once)
    asm volatile("cp.async.wait_group 0;" ::: "memory");
    __syncthreads();
    for (int i = tid; i < BM * Dv / 4; i += THREADS) {
        int r = i >> 4, c = (i & 15) * 4;
        uint32_t* p = sQ + r * LDSK + c;
        float4 f = *reinterpret_cast<const float4*>(p);
        p[0] = f2tf(f.x); p[1] = f2tf(f.y); p[2] = f2tf(f.z); p[3] = f2tf(f.w);
    }
    __syncthreads();

    const uint32_t* sQa0 = sQ + (wrow + g) * LDSK + t4;
    const uint32_t* sQa1 = sQ + (wrow + 16 + g) * LDSK + t4;
    const int rA0 = qbase + wrow + g;
    const int rA1 = qbase + wrow + 16 + g;

    const int srcA = (lane & 28) | (t4 >> 1);
    const int srcB = srcA + 2;
    const int sel  = t4 & 1;

    float ls[2][2] = {{0.f, 0.f}, {0.f, 0.f}};
    float o[2][8][4];
    #pragma unroll
    for (int mb = 0; mb < 2; mb++)
        #pragma unroll
        for (int dt = 0; dt < 8; dt++)
            o[mb][dt][0] = o[mb][dt][1] = o[mb][dt][2] = o[mb][dt][3] = 0.f;

    for (int kt = 0; kt < NKT; kt++) {
        const int cur = kt & 1;
        // prefetch next tile into the other buffer
        if (kt + 1 < NKT) {
            const uint32_t dk = sb + (cur ? SK0 : SK1);
            const uint32_t dv = sb + (cur ? SV0 : SV1);
            const float* ks = kp + (size_t)(kt + 1) * BN * Dv;
            const float* vs = vp + (size_t)(kt + 1) * BN * Dv;
            for (int i = tid; i < BN * Dv / 4; i += THREADS) {
                int r = i >> 4, c = (i & 15) * 4;
                cpa16(dk + (r * LDSK + c) * 4, ks + (size_t)r * Dv + c);
                cpa16(dv + (r * LDSK + c) * 4, vs + (size_t)r * Dv + c);
            }
            asm volatile("cp.async.commit_group;" ::: "memory");
            asm volatile("cp.async.wait_group 1;" ::: "memory");
        } else {
            asm volatile("cp.async.wait_group 0;" ::: "memory");
        }
        __syncthreads();

        const float* sK = (float*)(smem + (cur ? SK1 : SK0));
        const float* sV = (float*)(smem + (cur ? SV1 : SV0));

        // ---- QK ----
        float acc[2][8][4];
        #pragma unroll
        for (int mb = 0; mb < 2; mb++)
            #pragma unroll
            for (int nt = 0; nt < 8; nt++)
                acc[mb][nt][0] = acc[mb][nt][1] = acc[mb][nt][2] = acc[mb][nt][3] = 0.f;

        #pragma unroll
        for (int kk = 0; kk < 8; kk++) {
            uint32_t a0[4], a1[4];
            a0[0] = sQa0[kk * 8];                a1[0] = sQa1[kk * 8];
            a0[1] = sQa0[kk * 8 + 8 * LDSK];     a1[1] = sQa1[kk * 8 + 8 * LDSK];
            a0[2] = sQa0[kk * 8 + 4];            a1[2] = sQa1[kk * 8 + 4];
            a0[3] = sQa0[kk * 8 + 8 * LDSK + 4]; a1[3] = sQa1[kk * 8 + 8 * LDSK + 4];
            #pragma unroll
            for (int nt = 0; nt < 8; nt++) {
                const float* kb = sK + (nt * 8 + g) * LDSK + kk * 8 + t4;
                uint32_t b0 = f2tf(kb[0]), b1 = f2tf(kb[4]);
                mma8(acc[0][nt], a0, b0, b1);
                mma8(acc[1][nt], a1, b0, b1);
            }
        }

        // ---- epilogue: e = exp(masked score + bias), unnormalized streaming attn write ----
        #pragma unroll
        for (int mb = 0; mb < 2; mb++) {
            const int rowA = (mb ? rA1 : rA0);
            const int rowB = rowA + 8;
            #pragma unroll
            for (int nt = 0; nt < 8; nt++) {
                int col = kt * BN + nt * 8 + 2 * t4;
                float2 bA = *reinterpret_cast<const float2*>(biasp + (size_t)rowA * Sv + col);
                float2 bB = *reinterpret_cast<const float2*>(biasp + (size_t)rowB * Sv + col);
                int2 mA = *reinterpret_cast<const int2*>(maskp + (size_t)rowA * Sv + col);
                int2 mB = *reinterpret_cast<const int2*>(maskp + (size_t)rowB * Sv + col);
                float s0 = (mA.x ? acc[mb][nt][0] * 0.125f : NEG_INF) + bA.x;
                float s1 = (mA.y ? acc[mb][nt][1] * 0.125f : NEG_INF) + bA.y;
                float s2 = (mB.x ? acc[mb][nt][2] * 0.125f : NEG_INF) + bB.x;
                float s3 = (mB.y ? acc[mb][nt][3] * 0.125f : NEG_INF) + bB.y;
                float e0 = __expf(fminf(s0, 60.f));
                float e1 = __expf(fminf(s1, 60.f));
                float e2 = __expf(fminf(s2, 60.f));
                float e3 = __expf(fminf(s3, 60.f));
                st_cs2(ap + (size_t)rowA * Sv + col, e0, e1);
                st_cs2(ap + (size_t)rowB * Sv + col, e2, e3);
                ls[mb][0] += e0 + e1;
                ls[mb][1] += e2 + e3;
                acc[mb][nt][0] = e0; acc[mb][nt][1] = e1;
                acc[mb][nt][2] = e2; acc[mb][nt][3] = e3;
            }
        }

        // ---- PV: remap acc (C-frag) -> A-frag via shuffles, rna-round, accumulate O ----
        #pragma unroll
        for (int kk = 0; kk < 8; kk++) {
            uint32_t a0[4], a1[4];
            {
                float u0 = __shfl_sync(0xffffffffu, acc[0][kk][0], srcA);
                float u1 = __shfl_sync(0xffffffffu, acc[0][kk][1], srcA);
                float u2 = __shfl_sync(0xffffffffu, acc[0][kk][2], srcA);
                float u3 = __shfl_sync(0xffffffffu, acc[0][kk][3], srcA);
                float w0 = __shfl_sync(0xffffffffu, acc[0][kk][0], srcB);
                float w1 = __shfl_sync(0xffffffffu, acc[0][kk][1], srcB);
                float w2 = __shfl_sync(0xffffffffu, acc[0][kk][2], srcB);
                float w3 = __shfl_sync(0xffffffffu, acc[0][kk][3], srcB);
                a0[0] = f2tf(sel ? u1 : u0);  a0[1] = f2tf(sel ? u3 : u2);
                a0[2] = f2tf(sel ? w1 : w0);  a0[3] = f2tf(sel ? w3 : w2);
            }
            {
                float u0 = __shfl_sync(0xffffffffu, acc[1][kk][0], srcA);
                float u1 = __shfl_sync(0xffffffffu, acc[1][kk][1], srcA);
                float u2 = __shfl_sync(0xffffffffu, acc[1][kk][2], srcA);
                float u3 = __shfl_sync(0xffffffffu, acc[1][kk][3], srcA);
                float w0 = __shfl_sync(0xffffffffu, acc[1][kk][0], srcB);
                float w1 = __shfl_sync(0xffffffffu, acc[1][kk][1], srcB);
                float w2 = __shfl_sync(0xffffffffu, acc[1][kk][2], srcB);
                float w3 = __shfl_sync(0xffffffffu, acc[1][kk][3], srcB);
                a1[0] = f2tf(sel ? u1 : u0);  a1[1] = f2tf(sel ? u3 : u2);
                a1[2] = f2tf(sel ? w1 : w0);  a1[3] = f2tf(sel ? w3 : w2);
            }
            #pragma unroll
            for (int dt = 0; dt < 8; dt++) {
                const float* vb = sV + (kk * 8 + t4) * LDSK + dt * 8 + g;
                uint32_t b0 = f2tf(vb[0]), b1 = f2tf(vb[4 * LDSK]);
                mma8(o[0][dt], a0, b0, b1);
                mma8(o[1][dt], a1, b0, b1);
            }
        }
        __syncthreads();  // done reading bufs before next iter's prefetch overwrites
    }

    // ---- row sums -> inverses (reduce across t4 quad) ----
    #pragma unroll
    for (int mb = 0; mb < 2; mb++) {
        ls[mb][0] += __shfl_xor_sync(0xffffffffu, ls[mb][0], 1);
        ls[mb][0] += __shfl_xor_sync(0xffffffffu, ls[mb][0], 2);
        ls[mb][1] += __shfl_xor_sync(0xffffffffu, ls[mb][1], 1);
        ls[mb][1] += __shfl_xor_sync(0xffffffffu, ls[mb][1], 2);
    }
    const float il[2][2] = {{1.f / ls[0][0], 1.f / ls[0][1]},
                            {1.f / ls[1][0], 1.f / ls[1][1]}};

    // stash inverses for the normalize kernel
    if (t4 == 0) {
        #pragma unroll
        for (int mb = 0; mb < 2; mb++) {
            const int rowA = (mb ? rA1 : rA0);
            g_inv[bh * Sv + rowA]     = il[mb][0];
            g_inv[bh * Sv + rowA + 8] = il[mb][1];
        }
    }

    // ---- write O (normalized) ----
    #pragma unroll
    for (int mb = 0; mb < 2; mb++) {
        const int rowA = (mb ? rA1 : rA0);
        const int rowB = rowA + 8;
        #pragma unroll
        for (int dt = 0; dt < 8; dt++) {
            int col = dt * 8 + 2 * t4;
            *reinterpret_cast<float2*>(op + (size_t)rowA * Dv + col) =
                make_float2(o[mb][dt][0] * il[mb][0], o[mb][dt][1] * il[mb][0]);
            *reinterpret_cast<float2*>(op + (size_t)rowB * Dv + col) =
                make_float2(o[mb][dt][2] * il[mb][1], o[mb][dt][3] * il[mb][1]);
        }
    }
}

// ---- pass 2: attn[row] *= 1/lsum[row] (pure stream, single-touch hints) ----
__global__ __launch_bounds__(256)
void sdpa_normalize_kernel(float4* __restrict__ attn, int64_t total4)
{
    int64_t stride = (int64_t)gridDim.x * blockDim.x;
    for (int64_t i = (int64_t)blockIdx.x * blockDim.x + threadIdx.x; i < total4; i += stride) {
        float inv = g_inv[i >> 9];   // 512 float4 per 2048-col row
        float4 vv = __ldcs(attn + i);
        vv.x *= inv; vv.y *= inv; vv.z *= inv; vv.w *= inv;
        __stcs(attn + i, vv);
    }
}

extern "C" void kernel_launch(void* const* d_in, const int* in_sizes, int n_in,
                              void* d_out, int out_size)
{
    const float* q    = (const float*)d_in[0];
    const float* k    = (const float*)d_in[1];
    const float* v    = (const float*)d_in[2];
    const int*   mask = (const int*)d_in[3];
    const float* bias = (const float*)d_in[4];
    float* out = (float*)d_out;

    cudaFuncSetAttribute(ScaledDotProductAttention_30253749633177_kernel,
                         cudaFuncAttributeMaxDynamicSharedMemorySize, SMEM_TOTAL);

    dim3 grid(Bv * Hv, Sv / BM);   // x = all (b,h) for one qt -> mask+bias L2 co-residency
    ScaledDotProductAttention_30253749633177_kernel<<<grid, THREADS, SMEM_TOTAL>>>(
        q, k, v, mask, bias, out);

    float4* attn = (float4*)(out + (size_t)Bv * Hv * Sv * Dv);
    int64_t total4 = (int64_t)Bv * Hv * Sv * Sv / 4;
    sdpa_normalize_kernel<<<8192, 256>>>(attn, total4);
}